// round 5
// baseline (speedup 1.0000x reference)
#include <cuda_runtime.h>

// x is [8, 4, 1048576] fp32.
constexpr int T_IN  = 1048576;
constexpr int T_OUT = T_IN - 12;        // 1048564
constexpr int NVEC  = T_OUT / 4;        // 262141 float4 outputs per row
constexpr int ROWS  = 8 * 4;            // 32 rows
constexpr int TPB   = 256;
constexpr int KINT  = 4;                // interleaved float4 vectors per thread
constexpr int VPB   = TPB * KINT;       // 1024 output vectors per block
constexpr int BPR   = (NVEC + VPB - 1) / VPB;   // 256 blocks per row

// ---- packed f32x2 helpers (sm_103a) ----
__device__ __forceinline__ unsigned long long pack2(float lo, float hi) {
    unsigned long long r;
    asm("mov.b64 %0, {%1, %2};" : "=l"(r) : "f"(lo), "f"(hi));
    return r;
}
__device__ __forceinline__ void unpack2(unsigned long long v, float& lo, float& hi) {
    asm("mov.b64 {%0, %1}, %2;" : "=f"(lo), "=f"(hi) : "l"(v));
}
__device__ __forceinline__ unsigned long long ffma2(unsigned long long a,
                                                    unsigned long long b,
                                                    unsigned long long c) {
    unsigned long long d;
    asm("fma.rn.f32x2 %0, %1, %2, %3;" : "=l"(d) : "l"(a), "l"(b), "l"(c));
    return d;
}

__global__ __launch_bounds__(TPB, 2)
void stencil13_kernel(const float* __restrict__ x,
                      const float* __restrict__ fd,
                      const float* __restrict__ gauss,
                      float* __restrict__ out) {
    // Composite 13-tap kernel (fd ⊛ gauss), computed once per block.
    __shared__ float s_comp[13];
    if (threadIdx.x < 13) {
        float s = 0.0f;
        #pragma unroll
        for (int i = 0; i < 5; i++) {
            int j = (int)threadIdx.x - i;
            if (j >= 0 && j < 9) s += __ldg(fd + i) * __ldg(gauss + j);
        }
        s_comp[threadIdx.x] = s;
    }
    __syncthreads();

    const int row = blockIdx.y;
    const float* xrow = x + (long)row * T_IN;
    float*       orow = out + (long)row * T_OUT;

    const int v0 = blockIdx.x * VPB + threadIdx.x;

    // Front-batch all loads: up to 16 independent LDG.128, streaming hint.
    float4 va[KINT][4];
    bool   pr[KINT];
    #pragma unroll
    for (int j = 0; j < KINT; j++) {
        const int vj = v0 + j * TPB;
        pr[j] = (vj < NVEC);
        if (pr[j]) {
            const float4* xin = reinterpret_cast<const float4*>(xrow + 4L * vj);
            va[j][0] = __ldcs(xin + 0);
            va[j][1] = __ldcs(xin + 1);
            va[j][2] = __ldcs(xin + 2);
            va[j][3] = __ldcs(xin + 3);
        }
    }

    // Broadcast coefficient pairs (ck, ck), hoisted out of the tile loop.
    unsigned long long cc[13];
    #pragma unroll
    for (int k = 0; k < 13; k++) {
        float ck = s_comp[k];
        cc[k] = pack2(ck, ck);
    }

    #pragma unroll
    for (int j = 0; j < KINT; j++) {
        if (pr[j]) {
            float xs[16] = { va[j][0].x, va[j][0].y, va[j][0].z, va[j][0].w,
                             va[j][1].x, va[j][1].y, va[j][1].z, va[j][1].w,
                             va[j][2].x, va[j][2].y, va[j][2].z, va[j][2].w,
                             va[j][3].x, va[j][3].y, va[j][3].z, va[j][3].w };
            // Adjacent-pair operands p[k] = (xs[k], xs[k+1]).
            unsigned long long p[15];
            #pragma unroll
            for (int k = 0; k < 15; k++) p[k] = pack2(xs[k], xs[k + 1]);

            unsigned long long o01 = 0ULL;   // (0.0f, 0.0f)
            unsigned long long o23 = 0ULL;
            #pragma unroll
            for (int k = 0; k < 13; k++) {
                o01 = ffma2(p[k],     cc[k], o01);
                o23 = ffma2(p[k + 2], cc[k], o23);
            }

            float4 r;
            unpack2(o01, r.x, r.y);
            unpack2(o23, r.z, r.w);
            __stcs(reinterpret_cast<float4*>(orow) + (v0 + j * TPB), r);
        }
    }
}

extern "C" void kernel_launch(void* const* d_in, const int* in_sizes, int n_in,
                              void* d_out, int out_size) {
    const float* x     = (const float*)d_in[0];  // [8,4,1048576] f32
    const float* fd    = (const float*)d_in[1];  // [5]  f32
    const float* gauss = (const float*)d_in[2];  // [9]  f32
    float* out = (float*)d_out;                  // [8,4,1048564] f32

    dim3 grid(BPR, ROWS);
    stencil13_kernel<<<grid, TPB>>>(x, fd, gauss, out);
}

// round 6
// speedup vs baseline: 1.2755x; 1.2755x over previous
#include <cuda_runtime.h>
#include <cstdint>

// x is [8, 4, 1048576] fp32.
constexpr int T_IN   = 1048576;
constexpr int T_OUT  = T_IN - 12;        // 1048564
constexpr int NVEC   = T_OUT / 4;        // 262141 float4 outputs per row
constexpr int ROWS   = 8 * 4;            // 32 rows
constexpr int TPB    = 256;
constexpr int VPB    = 1024;             // output float4 vecs per block (4096 floats)
constexpr int BPR    = (NVEC + VPB - 1) / VPB;     // 256 blocks per row
constexpr int IN_FLOATS_FULL = VPB * 4 + 12;       // 4108 floats = 16432 B (mult of 16)

__device__ __forceinline__ uint32_t smem_u32(const void* p) {
    uint32_t a;
    asm("{ .reg .u64 t; cvta.to.shared.u64 t, %1; cvt.u32.u64 %0, t; }"
        : "=r"(a) : "l"(p));
    return a;
}

__global__ __launch_bounds__(TPB)
void stencil13_kernel(const float* __restrict__ x,
                      const float* __restrict__ fd,
                      const float* __restrict__ gauss,
                      float* __restrict__ out) {
    __shared__ alignas(16) float s_x[IN_FLOATS_FULL + 1];  // bulk-copy target
    __shared__ float s_comp[13];
    __shared__ alignas(8) uint64_t s_mbar;

    const int tid = threadIdx.x;
    const int row = blockIdx.y;
    const float* xrow = x + (long)row * T_IN;
    float*       orow = out + (long)row * T_OUT;

    const long in_base = 4096L * blockIdx.x;                 // first input float
    const int  nin     = (int)min((long)IN_FLOATS_FULL, (long)T_IN - in_base);
    const uint32_t mbar = smem_u32(&s_mbar);

    if (tid == 0) {
        asm volatile("mbarrier.init.shared.b64 [%0], 1;" :: "r"(mbar) : "memory");
    }
    // Composite 13-tap kernel (fd ⊛ gauss) while the copy is being set up.
    if (tid < 13) {
        float s = 0.0f;
        #pragma unroll
        for (int i = 0; i < 5; i++) {
            int j = tid - i;
            if (j >= 0 && j < 9) s += __ldg(fd + i) * __ldg(gauss + j);
        }
        s_comp[tid] = s;
    }
    __syncthreads();   // mbarrier + s_comp visible

    if (tid == 0) {
        uint32_t dst = smem_u32(s_x);
        uint32_t nbytes = (uint32_t)nin * 4u;
        asm volatile("mbarrier.arrive.expect_tx.shared.b64 _, [%0], %1;"
                     :: "r"(mbar), "r"(nbytes) : "memory");
        asm volatile(
            "cp.async.bulk.shared::cta.global.mbarrier::complete_tx::bytes "
            "[%0], [%1], %2, [%3];"
            :: "r"(dst), "l"(xrow + in_base), "r"(nbytes), "r"(mbar)
            : "memory");
    }

    // Wait for bulk copy (parity 0; barrier used once per block).
    {
        uint32_t done;
        asm volatile(
            "{\n\t"
            ".reg .pred p;\n\t"
            "mbarrier.try_wait.parity.acquire.cta.shared::cta.b64 p, [%1], 0;\n\t"
            "selp.b32 %0, 1, 0, p;\n\t"
            "}" : "=r"(done) : "r"(mbar) : "memory");
        if (!done) {
            asm volatile(
                "{\n\t"
                ".reg .pred P1;\n\t"
                "WL_%=:\n\t"
                "mbarrier.try_wait.parity.acquire.cta.shared::cta.b64 P1, [%0], 0, 0x989680;\n\t"
                "@P1 bra.uni WD_%=;\n\t"
                "bra.uni WL_%=;\n\t"
                "WD_%=:\n\t"
                "}" :: "r"(mbar) : "memory");
        }
    }

    float comp[13];
    #pragma unroll
    for (int k = 0; k < 13; k++) comp[k] = s_comp[k];

    const int gvbase = blockIdx.x * VPB;

    #pragma unroll
    for (int j = 0; j < 4; j++) {
        const int lv = tid + j * TPB;          // local output vec 0..1023
        const int gv = gvbase + lv;
        if (gv < NVEC) {
            const float4* sv = reinterpret_cast<const float4*>(s_x + 4 * lv);
            float4 a = sv[0], b = sv[1], c = sv[2], d = sv[3];
            float xs[16] = { a.x, a.y, a.z, a.w,  b.x, b.y, b.z, b.w,
                             c.x, c.y, c.z, c.w,  d.x, d.y, d.z, d.w };
            float o0 = 0.f, o1 = 0.f, o2 = 0.f, o3 = 0.f;
            #pragma unroll
            for (int k = 0; k < 13; k++) {
                const float ck = comp[k];
                o0 = fmaf(ck, xs[k + 0], o0);
                o1 = fmaf(ck, xs[k + 1], o1);
                o2 = fmaf(ck, xs[k + 2], o2);
                o3 = fmaf(ck, xs[k + 3], o3);
            }
            float4 r; r.x = o0; r.y = o1; r.z = o2; r.w = o3;
            __stcs(reinterpret_cast<float4*>(orow) + gv, r);
        }
    }
}

extern "C" void kernel_launch(void* const* d_in, const int* in_sizes, int n_in,
                              void* d_out, int out_size) {
    const float* x     = (const float*)d_in[0];  // [8,4,1048576] f32
    const float* fd    = (const float*)d_in[1];  // [5]  f32
    const float* gauss = (const float*)d_in[2];  // [9]  f32
    float* out = (float*)d_out;                  // [8,4,1048564] f32

    dim3 grid(BPR, ROWS);
    stencil13_kernel<<<grid, TPB>>>(x, fd, gauss, out);
}